// round 12
// baseline (speedup 1.0000x reference)
#include <cuda_runtime.h>
#include <stdint.h>

// ---------------------------------------------------------------------------
// octree_level matching the reference's ACTUAL semantics (JAX x64 disabled:
// _key overflows int32; wrapped key = ((x&255)<<24)|(y<<12)|z, signed order).
//   - parent identity collapses px -> sx = px & 255
//   - signed sort == lexicographic (sx^128, py, pz), negative half first
//   - rows with key<0 (sx>=128) are invalid: coords (-1,-1,-1), occ 0
//   - child (i,j,k) of valid parent (sx,py,pz) occupied <=> exists leaf with
//     (x&255, y, z) == (2sx+i, 2py+j, 2pz+k)
//
// parent bitmap: 2^26 cells, idx = (sp<<18)|(py<<9)|pz, sp=(px&255)^128 (8MB)
// leaf2 probe table (child-grouped): bit = (cell<<3)|m (32 MB),
//   cell = (((x&255)>>1)<<18)|((y>>1)<<9)|(z>>1), m = 4(x&1)+2(y&1)+(z&1)
//   -> a parent's 8-child occupancy is ONE byte of one word.
//
// Rank machinery: chunk = 1024 words. k_count sums per chunk (uint4 loads),
// k_scan exclusive-scans the 2048 chunk sums (invN = excl[1024], np = total).
// Fused k_emit_fill: blocks [0,1024) emit valid chunks (single uint4/thread,
// one warp scan, one __syncthreads); blocks [1024, 1024+FILLB) stream the
// constant rows [0,invN) and [np,n) concurrently.
//
// kernel_launch adapts to out_size (never writes beyond it):
//   out_size >= 11n : planar [parent_C float (3n) | occupancy float (8n)]
//   out_size ==  8n : occupancy only (float)
//   else            : parent_C only (int32)
// ---------------------------------------------------------------------------

#define LEAF2_WORDS (1u << 23)  // 2^28 bits -> 32 MB
#define PAR_WORDS   (1u << 21)  // 2^26 bits ->  8 MB
#define TPB         256
#define CHUNK_WORDS 1024
#define NCHUNKS     (PAR_WORDS / CHUNK_WORDS)   // 2048
#define EMITB       (NCHUNKS / 2)               // 1024 valid-half chunks
#define FILLB       2048

__device__ unsigned int g_leaf2[LEAF2_WORDS];
__device__ unsigned int g_par_bits[PAR_WORDS];
__device__ unsigned int g_chunk_sums[NCHUNKS];
__device__ unsigned int g_chunk_excl[NCHUNKS + 1];  // [NCHUNKS] = np
__device__ unsigned int g_np;

__device__ __forceinline__ int clamp1023(float v) {
    int x = (int)floorf(v);
    x = x < 0 ? 0 : x;
    return x > 1023 ? 1023 : x;
}

// --- scatter: parent bitmap only -------------------------------------------
__global__ void k_scatter_par(const float* __restrict__ leaf, int n) {
    int i = blockIdx.x * blockDim.x + threadIdx.x;
    if (i >= n) return;
    int x = clamp1023(leaf[3 * i + 0]);
    int y = clamp1023(leaf[3 * i + 1]);
    int z = clamp1023(leaf[3 * i + 2]);
    unsigned sp = (((unsigned)(x >> 1)) & 255u) ^ 128u;
    unsigned pidx = (sp << 18) | ((unsigned)(y >> 1) << 9) | (unsigned)(z >> 1);
    atomicOr(&g_par_bits[pidx >> 5], 1u << (pidx & 31));
}

// --- scatter: parent bitmap + child-grouped probe table --------------------
__global__ void k_scatter_full(const float* __restrict__ leaf, int n) {
    int i = blockIdx.x * blockDim.x + threadIdx.x;
    if (i >= n) return;
    int x = clamp1023(leaf[3 * i + 0]);
    int y = clamp1023(leaf[3 * i + 1]);
    int z = clamp1023(leaf[3 * i + 2]);
    unsigned sxp = ((unsigned)(x & 255)) >> 1;
    unsigned cell = (sxp << 18) | ((unsigned)(y >> 1) << 9) | (unsigned)(z >> 1);
    unsigned m = (((unsigned)x & 1u) << 2) | (((unsigned)y & 1u) << 1) | ((unsigned)z & 1u);
    atomicOr(&g_leaf2[cell >> 2], 1u << (((cell & 3u) << 3) | m));
    unsigned sp = (((unsigned)(x >> 1)) & 255u) ^ 128u;
    unsigned pidx = (sp << 18) | ((unsigned)(y >> 1) << 9) | (unsigned)(z >> 1);
    atomicOr(&g_par_bits[pidx >> 5], 1u << (pidx & 31));
}

// --- per-chunk popcount (uint4 loads) --------------------------------------
__global__ void k_count() {
    __shared__ unsigned int warp_sums[TPB / 32];
    unsigned t = threadIdx.x;
    const uint4* pw = (const uint4*)g_par_bits;
    uint4 v = pw[blockIdx.x * (CHUNK_WORDS / 4) + t];
    unsigned s = __popc(v.x) + __popc(v.y) + __popc(v.z) + __popc(v.w);
#pragma unroll
    for (int o = 16; o; o >>= 1) s += __shfl_down_sync(0xffffffffu, s, o);
    if ((t & 31) == 0) warp_sums[t >> 5] = s;
    __syncthreads();
    if (t == 0) {
        unsigned tot = 0;
#pragma unroll
        for (int w = 0; w < TPB / 32; w++) tot += warp_sums[w];
        g_chunk_sums[blockIdx.x] = tot;
    }
}

// --- exclusive scan of 2048 chunk sums (one block, 1024 threads) -----------
__global__ void k_scan() {
    __shared__ unsigned int ps[NCHUNKS / 2];
    unsigned t = threadIdx.x;
    unsigned v0 = g_chunk_sums[2 * t], v1 = g_chunk_sums[2 * t + 1];
    unsigned pair = v0 + v1;
    ps[t] = pair;
    __syncthreads();
    for (int o = 1; o < NCHUNKS / 2; o <<= 1) {
        unsigned x = (t >= (unsigned)o) ? ps[t - o] : 0u;
        __syncthreads();
        ps[t] += x;
        __syncthreads();
    }
    unsigned pairExcl = ps[t] - pair;
    g_chunk_excl[2 * t + 0] = pairExcl;
    g_chunk_excl[2 * t + 1] = pairExcl + v0;
    if (t == NCHUNKS / 2 - 1) {
        g_chunk_excl[NCHUNKS] = ps[t];
        g_np = ps[t];
    }
}

// ---------------------------------------------------------------------------
// Fused emit + fill.
// Blocks [0, EMITB): emit valid chunk EMITB + bid. One uint4 (4 words = 128
//   parent cells) per thread, one warp scan + one block combine.
// Blocks [EMITB, EMITB+FILLB): grid-stride constant fill of rows [0,invN)
//   and [np, n).
// MODE 0: int32 coords; MODE 1: float coords + occ; MODE 2: occ only.
// ---------------------------------------------------------------------------
template <int MODE>
__global__ void k_emit_fill(void* __restrict__ out_raw, int n) {
    int*   out_i   = (int*)out_raw;
    float* out_f   = (float*)out_raw;
    float* out_occ = (MODE == 1) ? out_f + 3ull * (unsigned long long)n : out_f;
    unsigned t = threadIdx.x;

    if (blockIdx.x < EMITB) {
        // ---------------- emit ----------------
        __shared__ unsigned int warp_sc[TPB / 32];
        unsigned lane = t & 31, wrp = t >> 5;
        unsigned chunk = EMITB + blockIdx.x;

        const uint4* pw = (const uint4*)g_par_bits;
        uint4 v = pw[chunk * (CHUNK_WORDS / 4) + t];
        unsigned pc[4] = {__popc(v.x), __popc(v.y), __popc(v.z), __popc(v.w)};
        unsigned p = pc[0] + pc[1] + pc[2] + pc[3];

        unsigned incl = p;                         // warp-inclusive scan
#pragma unroll
        for (int o = 1; o < 32; o <<= 1) {
            unsigned x = __shfl_up_sync(0xffffffffu, incl, o);
            if (lane >= (unsigned)o) incl += x;
        }
        if (lane == 31) warp_sc[wrp] = incl;
        __syncthreads();
        unsigned warp_off = 0;
#pragma unroll
        for (unsigned ww = 0; ww < TPB / 32; ww++)
            if (ww < wrp) warp_off += warp_sc[ww];
        unsigned r = g_chunk_excl[chunk] + warp_off + incl - p;

        unsigned w0 = chunk * CHUNK_WORDS + t * 4;
        unsigned words[4] = {v.x, v.y, v.z, v.w};
#pragma unroll
        for (int j = 0; j < 4; j++) {
            unsigned bb = words[j];
            while (bb) {
                int b = __ffs(bb) - 1;
                bb &= bb - 1;
                unsigned idx = ((w0 + (unsigned)j) << 5) | (unsigned)b;
                unsigned cell = idx - (1u << 25);  // sp>=128 half -> sx<128
                unsigned sx = cell >> 18;
                unsigned py = (cell >> 9) & 511u;
                unsigned pz = cell & 511u;

                if (MODE == 0) {
                    unsigned long long r3 = 3ull * r;
                    out_i[r3 + 0] = (int)sx;
                    out_i[r3 + 1] = (int)py;
                    out_i[r3 + 2] = (int)pz;
                } else if (MODE == 1) {
                    unsigned long long r3 = 3ull * r;
                    out_f[r3 + 0] = (float)sx;
                    out_f[r3 + 1] = (float)py;
                    out_f[r3 + 2] = (float)pz;
                }
                if (MODE != 0) {
                    unsigned lw = g_leaf2[cell >> 2];
                    unsigned byt = (lw >> ((cell & 3u) << 3)) & 255u;
                    float4 o0 = make_float4((float)(byt & 1u), (float)((byt >> 1) & 1u),
                                            (float)((byt >> 2) & 1u), (float)((byt >> 3) & 1u));
                    float4 o1 = make_float4((float)((byt >> 4) & 1u), (float)((byt >> 5) & 1u),
                                            (float)((byt >> 6) & 1u), (float)((byt >> 7) & 1u));
                    float4* dst = (float4*)(out_occ + 8ull * r);
                    dst[0] = o0;
                    dst[1] = o1;
                }
                r++;
            }
        }
    } else {
        // ---------------- fill ----------------
        unsigned invN = g_chunk_excl[EMITB];        // rows in negative-key half
        unsigned np   = g_chunk_excl[NCHUNKS];      // total real rows
        unsigned fb = blockIdx.x - EMITB;
        float4 z4 = make_float4(0.f, 0.f, 0.f, 0.f);
        for (unsigned i = fb * TPB + t; i < (unsigned)n; i += FILLB * TPB) {
            if (i >= invN && i < np) continue;      // valid row: emit owns it
            if (MODE == 0) {
                unsigned long long i3 = 3ull * i;
                out_i[i3 + 0] = -1; out_i[i3 + 1] = -1; out_i[i3 + 2] = -1;
            } else if (MODE == 1) {
                unsigned long long i3 = 3ull * i;
                out_f[i3 + 0] = -1.0f; out_f[i3 + 1] = -1.0f; out_f[i3 + 2] = -1.0f;
                float4* oo = (float4*)(out_occ + 8ull * i);
                oo[0] = z4; oo[1] = z4;
            } else {
                float4* oo = (float4*)(out_occ + 8ull * i);
                oo[0] = z4; oo[1] = z4;
            }
        }
    }
}

extern "C" void kernel_launch(void* const* d_in, const int* in_sizes, int n_in,
                              void* d_out, int out_size) {
    const float* leaf = (const float*)d_in[0];
    int n = in_sizes[0] / 3;
    int grid_n = (n + TPB - 1) / TPB;

    void* pp = nullptr;
    cudaGetSymbolAddress(&pp, g_par_bits);
    cudaMemsetAsync(pp, 0, (size_t)PAR_WORDS * sizeof(unsigned int));

    bool need_occ = (out_size >= 11 * n) || (out_size == 8 * n);
    if (need_occ) {
        void* pl = nullptr;
        cudaGetSymbolAddress(&pl, g_leaf2);
        cudaMemsetAsync(pl, 0, (size_t)LEAF2_WORDS * sizeof(unsigned int));
        k_scatter_full<<<grid_n, TPB>>>(leaf, n);
    } else {
        k_scatter_par<<<grid_n, TPB>>>(leaf, n);
    }

    k_count<<<NCHUNKS, TPB>>>();
    k_scan<<<1, NCHUNKS / 2>>>();

    if (out_size >= 11 * n) {
        k_emit_fill<1><<<EMITB + FILLB, TPB>>>(d_out, n);
    } else if (out_size == 8 * n) {
        k_emit_fill<2><<<EMITB + FILLB, TPB>>>(d_out, n);
    } else {
        k_emit_fill<0><<<EMITB + FILLB, TPB>>>(d_out, n);
    }
}

// round 13
// speedup vs baseline: 1.0770x; 1.0770x over previous
#include <cuda_runtime.h>
#include <stdint.h>

// ---------------------------------------------------------------------------
// octree_level matching the reference's ACTUAL semantics (JAX x64 disabled:
// _key overflows int32; wrapped key = ((x&255)<<24)|(y<<12)|z, signed order).
//   - parent identity collapses px -> sx = px & 255
//   - signed sort == lexicographic (sx^128, py, pz), negative half first
//   - rows with key<0 (sx>=128) are invalid: coords (-1,-1,-1), occ 0
//   - child (i,j,k) of valid parent (sx,py,pz) occupied <=> exists leaf with
//     (x&255, y, z) == (2sx+i, 2py+j, 2pz+k)
//
// parent bitmap: 2^26 cells, idx = (sp<<18)|(py<<9)|pz, sp=(px&255)^128 (8MB)
// leaf2 probe table (child-grouped): bit = (cell<<3)|m (32 MB),
//   cell = (((x&255)>>1)<<18)|((y>>1)<<9)|(z>>1), m = 4(x&1)+2(y&1)+(z&1)
//   -> a parent's 8-child occupancy is ONE byte of one word.
//
// Ranks at 256-word chunk granularity (8192 chunks). k_emit_fill: each of
// 4096 blocks (a) compacts its valid-half chunk's set bits to shared, then
// writes rows coalesced (row-per-thread), and (b) grid-strides a slice of
// the constant regions [0,invN) and [np,n). Uniform per-block work -> real
// overlap of emit and fill.
//
// kernel_launch adapts to out_size (never writes beyond it):
//   out_size >= 11n : planar [parent_C float (3n) | occupancy float (8n)]
//   out_size ==  8n : occupancy only (float)
//   else            : parent_C only (int32)
// ---------------------------------------------------------------------------

#define LEAF2_WORDS (1u << 23)  // 2^28 bits -> 32 MB
#define PAR_WORDS   (1u << 21)  // 2^26 bits ->  8 MB
#define TPB         256
#define CWORDS      256                     // words per chunk
#define NCH         (PAR_WORDS / CWORDS)    // 8192 chunks
#define VCH         (NCH / 2)               // 4096 valid-half chunks
#define SCAN_T      1024                    // k_scan threads (8 vals each)

__device__ unsigned int g_leaf2[LEAF2_WORDS];
__device__ unsigned int g_par_bits[PAR_WORDS];
__device__ unsigned int g_chunk_sums[NCH];
__device__ unsigned int g_chunk_excl[NCH + 1];   // [NCH] = np, [VCH] = invN

__device__ __forceinline__ int clamp1023(float v) {
    int x = (int)floorf(v);
    x = x < 0 ? 0 : x;
    return x > 1023 ? 1023 : x;
}

// --- scatter: parent bitmap only -------------------------------------------
__global__ void k_scatter_par(const float* __restrict__ leaf, int n) {
    int i = blockIdx.x * blockDim.x + threadIdx.x;
    if (i >= n) return;
    int x = clamp1023(leaf[3 * i + 0]);
    int y = clamp1023(leaf[3 * i + 1]);
    int z = clamp1023(leaf[3 * i + 2]);
    unsigned sp = (((unsigned)(x >> 1)) & 255u) ^ 128u;
    unsigned pidx = (sp << 18) | ((unsigned)(y >> 1) << 9) | (unsigned)(z >> 1);
    atomicOr(&g_par_bits[pidx >> 5], 1u << (pidx & 31));
}

// --- scatter: parent bitmap + child-grouped probe table --------------------
__global__ void k_scatter_full(const float* __restrict__ leaf, int n) {
    int i = blockIdx.x * blockDim.x + threadIdx.x;
    if (i >= n) return;
    int x = clamp1023(leaf[3 * i + 0]);
    int y = clamp1023(leaf[3 * i + 1]);
    int z = clamp1023(leaf[3 * i + 2]);
    unsigned sxp = ((unsigned)(x & 255)) >> 1;
    unsigned cell = (sxp << 18) | ((unsigned)(y >> 1) << 9) | (unsigned)(z >> 1);
    unsigned m = (((unsigned)x & 1u) << 2) | (((unsigned)y & 1u) << 1) | ((unsigned)z & 1u);
    atomicOr(&g_leaf2[cell >> 2], 1u << (((cell & 3u) << 3) | m));
    unsigned sp = (((unsigned)(x >> 1)) & 255u) ^ 128u;
    unsigned pidx = (sp << 18) | ((unsigned)(y >> 1) << 9) | (unsigned)(z >> 1);
    atomicOr(&g_par_bits[pidx >> 5], 1u << (pidx & 31));
}

// --- per-chunk popcount: 256 threads, 1 word each --------------------------
__global__ void k_count() {
    __shared__ unsigned int warp_sums[TPB / 32];
    unsigned t = threadIdx.x;
    unsigned s = __popc(g_par_bits[blockIdx.x * CWORDS + t]);
#pragma unroll
    for (int o = 16; o; o >>= 1) s += __shfl_down_sync(0xffffffffu, s, o);
    if ((t & 31) == 0) warp_sums[t >> 5] = s;
    __syncthreads();
    if (t == 0) {
        unsigned tot = 0;
#pragma unroll
        for (int w = 0; w < TPB / 32; w++) tot += warp_sums[w];
        g_chunk_sums[blockIdx.x] = tot;
    }
}

// --- exclusive scan of 8192 chunk sums (one block, 1024 thr, 8 vals each) --
__global__ void k_scan() {
    __shared__ unsigned int sh[SCAN_T];
    unsigned t = threadIdx.x;
    unsigned v[8], s = 0;
#pragma unroll
    for (int j = 0; j < 8; j++) { v[j] = g_chunk_sums[8 * t + j]; s += v[j]; }
    sh[t] = s;
    __syncthreads();
    for (int o = 1; o < SCAN_T; o <<= 1) {
        unsigned x = (t >= (unsigned)o) ? sh[t - o] : 0u;
        __syncthreads();
        sh[t] += x;
        __syncthreads();
    }
    unsigned base = sh[t] - s;               // exclusive over thread groups
#pragma unroll
    for (int j = 0; j < 8; j++) { g_chunk_excl[8 * t + j] = base; base += v[j]; }
    if (t == SCAN_T - 1) g_chunk_excl[NCH] = sh[t];
}

// ---------------------------------------------------------------------------
// Fused emit + fill: grid = VCH blocks. Each block:
//  (a) compacts set bits of valid chunk VCH+bid into shared, then writes rows
//      coalesced, one row per thread per stride;
//  (b) grid-strides its slice of the constant regions [0,invN) and [np,n).
// MODE 0: int32 coords; MODE 1: float coords + occ; MODE 2: occ only.
// ---------------------------------------------------------------------------
template <int MODE>
__global__ void k_emit_fill(void* __restrict__ out_raw, int n) {
    __shared__ unsigned int buf[CWORDS * 32];     // worst case 8192 cells, 32 KB
    __shared__ unsigned int warp_sc[TPB / 32];

    int*   out_i   = (int*)out_raw;
    float* out_f   = (float*)out_raw;
    float* out_occ = (MODE == 1) ? out_f + 3ull * (unsigned long long)n : out_f;
    unsigned t = threadIdx.x;
    unsigned lane = t & 31, wrp = t >> 5;

    // ---------------- emit: phase 1, compact ----------------
    unsigned chunk = VCH + blockIdx.x;
    unsigned w = chunk * CWORDS + t;
    unsigned bits = g_par_bits[w];
    unsigned p = __popc(bits);

    unsigned incl = p;
#pragma unroll
    for (int o = 1; o < 32; o <<= 1) {
        unsigned x = __shfl_up_sync(0xffffffffu, incl, o);
        if (lane >= (unsigned)o) incl += x;
    }
    if (lane == 31) warp_sc[wrp] = incl;
    __syncthreads();
    unsigned warp_off = 0;
#pragma unroll
    for (unsigned ww = 0; ww < TPB / 32; ww++)
        if (ww < wrp) warp_off += warp_sc[ww];
    unsigned pos = warp_off + incl - p;           // block-local rank

    unsigned cell_base = (w << 5) - (1u << 25);   // valid half: sp>=128 -> sx<128
    unsigned bb = bits;
    while (bb) {
        int b = __ffs(bb) - 1;
        bb &= bb - 1;
        buf[pos++] = cell_base | (unsigned)b;
    }
    __syncthreads();

    unsigned mrows = 0;
#pragma unroll
    for (unsigned ww = 0; ww < TPB / 32; ww++) mrows += warp_sc[ww];
    unsigned r0 = g_chunk_excl[chunk];

    // ---------------- emit: phase 2, coalesced row writes ----------------
    for (unsigned i = t; i < mrows; i += TPB) {
        unsigned cell = buf[i];
        unsigned r = r0 + i;
        unsigned sx = cell >> 18;
        unsigned py = (cell >> 9) & 511u;
        unsigned pz = cell & 511u;

        if (MODE == 0) {
            unsigned long long r3 = 3ull * r;
            out_i[r3 + 0] = (int)sx;
            out_i[r3 + 1] = (int)py;
            out_i[r3 + 2] = (int)pz;
        } else if (MODE == 1) {
            unsigned long long r3 = 3ull * r;
            out_f[r3 + 0] = (float)sx;
            out_f[r3 + 1] = (float)py;
            out_f[r3 + 2] = (float)pz;
        }
        if (MODE != 0) {
            unsigned lw = g_leaf2[cell >> 2];
            unsigned byt = (lw >> ((cell & 3u) << 3)) & 255u;
            float4 o0 = make_float4((float)(byt & 1u), (float)((byt >> 1) & 1u),
                                    (float)((byt >> 2) & 1u), (float)((byt >> 3) & 1u));
            float4 o1 = make_float4((float)((byt >> 4) & 1u), (float)((byt >> 5) & 1u),
                                    (float)((byt >> 6) & 1u), (float)((byt >> 7) & 1u));
            float4* dst = (float4*)(out_occ + 8ull * r);
            dst[0] = o0;
            dst[1] = o1;
        }
    }

    // ---------------- fill: constant regions ----------------
    unsigned invN = g_chunk_excl[VCH];            // rows of negative-key half
    unsigned np   = g_chunk_excl[NCH];            // total real rows
    float4 z4 = make_float4(0.f, 0.f, 0.f, 0.f);
    const unsigned stride = VCH * TPB;

    for (unsigned i = blockIdx.x * TPB + t; i < invN; i += stride) {
        if (MODE == 0) {
            unsigned long long i3 = 3ull * i;
            out_i[i3 + 0] = -1; out_i[i3 + 1] = -1; out_i[i3 + 2] = -1;
        } else if (MODE == 1) {
            unsigned long long i3 = 3ull * i;
            out_f[i3 + 0] = -1.0f; out_f[i3 + 1] = -1.0f; out_f[i3 + 2] = -1.0f;
            float4* oo = (float4*)(out_occ + 8ull * i);
            oo[0] = z4; oo[1] = z4;
        } else {
            float4* oo = (float4*)(out_occ + 8ull * i);
            oo[0] = z4; oo[1] = z4;
        }
    }
    for (unsigned i = np + blockIdx.x * TPB + t; i < (unsigned)n; i += stride) {
        if (MODE == 0) {
            unsigned long long i3 = 3ull * i;
            out_i[i3 + 0] = -1; out_i[i3 + 1] = -1; out_i[i3 + 2] = -1;
        } else if (MODE == 1) {
            unsigned long long i3 = 3ull * i;
            out_f[i3 + 0] = -1.0f; out_f[i3 + 1] = -1.0f; out_f[i3 + 2] = -1.0f;
            float4* oo = (float4*)(out_occ + 8ull * i);
            oo[0] = z4; oo[1] = z4;
        } else {
            float4* oo = (float4*)(out_occ + 8ull * i);
            oo[0] = z4; oo[1] = z4;
        }
    }
}

extern "C" void kernel_launch(void* const* d_in, const int* in_sizes, int n_in,
                              void* d_out, int out_size) {
    const float* leaf = (const float*)d_in[0];
    int n = in_sizes[0] / 3;
    int grid_n = (n + TPB - 1) / TPB;

    void* pp = nullptr;
    cudaGetSymbolAddress(&pp, g_par_bits);
    cudaMemsetAsync(pp, 0, (size_t)PAR_WORDS * sizeof(unsigned int));

    bool need_occ = (out_size >= 11 * n) || (out_size == 8 * n);
    if (need_occ) {
        void* pl = nullptr;
        cudaGetSymbolAddress(&pl, g_leaf2);
        cudaMemsetAsync(pl, 0, (size_t)LEAF2_WORDS * sizeof(unsigned int));
        k_scatter_full<<<grid_n, TPB>>>(leaf, n);
    } else {
        k_scatter_par<<<grid_n, TPB>>>(leaf, n);
    }

    k_count<<<NCH, TPB>>>();
    k_scan<<<1, SCAN_T>>>();

    if (out_size >= 11 * n) {
        k_emit_fill<1><<<VCH, TPB>>>(d_out, n);
    } else if (out_size == 8 * n) {
        k_emit_fill<2><<<VCH, TPB>>>(d_out, n);
    } else {
        k_emit_fill<0><<<VCH, TPB>>>(d_out, n);
    }
}